// round 1
// baseline (speedup 1.0000x reference)
#include <cuda_runtime.h>
#include <math.h>

#define BB 20
#define LL 20
#define VV 100000
#define PSTRIDE 401   // 400 P-entries per batch, padded (401 mod 32 = 17, odd -> conflict-free lane stride)
#define MSTRIDE 21    // mask/idx row stride (odd -> conflict-free)

__global__ __launch_bounds__(1024, 1)
void calcs_kernel(const float* __restrict__ tp,
                  const int*   __restrict__ hl,
                  float* __restrict__ out) {
    __shared__ float P[BB * PSTRIDE];      // 20*401*4 = 32080 B
    __shared__ float mask_s[BB * MSTRIDE];
    __shared__ int   idx_s[BB * MSTRIDE];
    __shared__ float calcs_s[BB];

    const int tid = threadIdx.x;

    // --- load labels, build mask + clipped gather index ---
    if (tid < BB * LL) {
        int b = tid / LL;
        int k = tid % LL;
        int h = hl[tid];
        mask_s[b * MSTRIDE + k] = (h >= 0) ? 1.0f : 0.0f;
        int c = h < 0 ? 0 : (h >= VV ? VV - 1 : h);
        idx_s[b * MSTRIDE + k] = c;
    }
    __syncthreads();

    // --- cooperative gather: P[b, j*L+k] = tp[b, j, idx[b,k]] ---
    // 8000 scattered loads across 1024 threads -> ~8 independent loads/thread (MLP hides DRAM latency)
    for (int e = tid; e < BB * LL * LL; e += blockDim.x) {
        int b = e / (LL * LL);
        int r = e - b * (LL * LL);
        int j = r / LL;
        int k = r - j * LL;
        P[b * PSTRIDE + r] =
            tp[(size_t)b * (LL * VV) + (size_t)j * VV + idx_s[b * MSTRIDE + k]];
    }
    __syncthreads();

    // --- DP: lane b (warp 0) handles batch b ---
    if (tid < BB) {
        const int b = tid;
        const float* __restrict__ Pb = &P[b * PSTRIDE];
        const float* __restrict__ Mb = &mask_s[b * MSTRIDE];

        int len = 0;
        #pragma unroll
        for (int k = 0; k < LL; k++) len += (Mb[k] > 0.0f) ? 1 : 0;

        float prev[LL + 1];
        float cur[LL + 1];
        #pragma unroll
        for (int k = 0; k <= LL; k++) prev[k] = 0.0f;

        float final_v = 0.0f;   // dp[0][0] covers len==0

        for (int j = 0; j < LL; j++) {
            float mj = Mb[j];
            cur[0] = 0.0f;
            float left = 0.0f;
            #pragma unroll
            for (int k = 0; k < LL; k++) {
                float p  = Pb[j * LL + k];
                float mk = Mb[k];
                float val = p * (prev[k] + 1.0f)
                          + (1.0f - p) * fmaxf(left, prev[k + 1]);
                val = (mj * mk > 0.0f) ? val : 0.0f;
                cur[k + 1] = val;
                left = val;
                if ((j + 1 == len) && (k + 1 == len)) final_v = val;
            }
            #pragma unroll
            for (int k = 0; k <= LL; k++) prev[k] = cur[k];
        }

        calcs_s[b] = -logf(final_v / (float)len);
    }
    __syncthreads();

    if (tid == 0) {
        float s = 0.0f;
        #pragma unroll
        for (int b = 0; b < BB; b++) s += calcs_s[b];
        out[0] = s / (float)BB;
    }
}

extern "C" void kernel_launch(void* const* d_in, const int* in_sizes, int n_in,
                              void* d_out, int out_size) {
    const float* tp = (const float*)d_in[0];   // topic_prob [B, L, V] f32
    const int*   hl = (const int*)d_in[1];     // hard_label [B, L] i32
    float* out = (float*)d_out;
    calcs_kernel<<<1, 1024>>>(tp, hl, out);
}

// round 4
// speedup vs baseline: 1.3851x; 1.3851x over previous
#include <cuda_runtime.h>
#include <math.h>

#define BB 20
#define LL 20
#define VV 100000

__device__ float g_calcs[BB];
__device__ int   g_count = 0;   // reset by the last block each launch -> replay-safe

__global__ void calcs_fused(const float* __restrict__ tp,
                            const int*   __restrict__ hl,
                            float* __restrict__ out) {
    __shared__ float Ps[LL * LL];   // a  = m_j*m_k * p
    __shared__ float M2[LL * LL];   // m_j*m_k
    __shared__ float ms[LL];
    __shared__ int   idxs[LL];
    __shared__ int   len_s;

    const int b = blockIdx.x;
    const int t = threadIdx.x;

    // labels for this batch
    if (t < LL) {
        int h = hl[b * LL + t];
        ms[t]   = (h >= 0) ? 1.0f : 0.0f;
        idxs[t] = h < 0 ? 0 : (h >= VV ? VV - 1 : h);
    }
    __syncthreads();

    // gather this batch's 400 probabilities (each block hits a different SM's
    // L1tex queue -> chip-parallel gather instead of single-SM serialization)
    if (t < LL * LL) {
        int j = t / LL, k = t - j * LL;
        float p  = tp[(size_t)b * (LL * VV) + (size_t)j * VV + idxs[k]];
        float m2 = ms[j] * ms[k];
        Ps[t] = m2 * p;
        M2[t] = m2;
    }
    if (t == 0) {
        int len = 0;
        #pragma unroll
        for (int k = 0; k < LL; k++) len += (ms[k] > 0.0f) ? 1 : 0;
        len_s = len;
    }
    __syncthreads();

    // serial DP, one thread per batch; chain = fmax -> ffma (8 cyc/step)
    if (t == 0) {
        const int len = len_s;
        float prev[LL + 1];
        #pragma unroll
        for (int k = 0; k <= LL; k++) prev[k] = 0.0f;

        float final_v = 0.0f;   // dp[0][0] covers len==0

        for (int j = 0; j < LL; j++) {
            // off-critical-path per-row precompute:
            //   dd[k] = a*(prev[k]+1),  cc[k] = m2 - a  (== m*(1-p))
            float dd[LL], cc[LL];
            #pragma unroll
            for (int k = 0; k < LL; k++) {
                float a = Ps[j * LL + k];
                dd[k] = a * (prev[k] + 1.0f);
                cc[k] = M2[j * LL + k] - a;
            }
            // critical chain: left = cc*max(left, up) + dd
            float left = 0.0f;
            #pragma unroll
            for (int k = 0; k < LL; k++) {
                float up  = prev[k + 1];
                float tmx = fmaxf(left, up);
                left = fmaf(cc[k], tmx, dd[k]);
                prev[k + 1] = left;            // in-place: up already consumed
                if ((j + 1 == len) && (k + 1 == len)) final_v = left;
            }
        }

        g_calcs[b] = -logf(final_v / (float)len);
        __threadfence();
        int ticket = atomicAdd(&g_count, 1);
        if (ticket == BB - 1) {
            // deterministic ordered reduction by the last-arriving block
            volatile float* gc = g_calcs;
            float s = 0.0f;
            #pragma unroll
            for (int i = 0; i < BB; i++) s += gc[i];
            out[0] = s / (float)BB;
            g_count = 0;   // re-arm for next graph replay
        }
    }
}

extern "C" void kernel_launch(void* const* d_in, const int* in_sizes, int n_in,
                              void* d_out, int out_size) {
    const float* tp = (const float*)d_in[0];   // topic_prob [B, L, V] f32
    const int*   hl = (const int*)d_in[1];     // hard_label [B, L] i32
    float* out = (float*)d_out;
    calcs_fused<<<BB, LL * LL>>>(tp, hl, out);
}

// round 5
// speedup vs baseline: 1.7059x; 1.2316x over previous
#include <cuda_runtime.h>
#include <math.h>

#define BB 20
#define LL 20
#define VV 100000

__device__ float g_calcs[BB];
__device__ int   g_count = 0;   // reset by the last block each launch -> replay-safe

__global__ __launch_bounds__(LL * LL, 1)
void calcs_fused(const float* __restrict__ tp,
                 const int*   __restrict__ hl,
                 float* __restrict__ out) {
    __shared__ float As[LL * LL];   // a = m_j*m_k * p
    __shared__ float Cs[LL * LL];   // c = m_j*m_k - a   (== m*(1-p) when masked)
    __shared__ int   len_s;

    const int b = blockIdx.x;
    const int t = threadIdx.x;
    const int j = t / LL;
    const int k = t - j * LL;

    // Per-thread label loads (both hit the same 128B line -> L1 broadcast).
    // Gather load issues immediately after: 2 dependent global round trips total.
    const int hj = hl[b * LL + j];
    const int hk = hl[b * LL + k];
    const float m2 = (hj >= 0 && hk >= 0) ? 1.0f : 0.0f;
    const int idx = hk < 0 ? 0 : (hk >= VV ? VV - 1 : hk);

    const float p = tp[(size_t)b * (LL * VV) + (size_t)j * VV + idx];
    const float a = m2 * p;
    As[t] = a;
    Cs[t] = m2 - a;

    // barrier + popcount in one: count of valid labels (row j==0 holds each k once)
    int cnt = __syncthreads_count((j == 0 && hk >= 0) ? 1 : 0);
    if (t == 0) len_s = cnt;

    // serial DP, thread 0; critical chain per step = fmax(4) -> ffma(4)
    if (t == 0) {
        const int len = len_s;
        float prev[LL + 1];
        #pragma unroll
        for (int i = 0; i <= LL; i++) prev[i] = 0.0f;

        float final_v = 0.0f;   // dp[0][0] covers len==0

        #pragma unroll 1
        for (int jj = 0; jj < LL; jj++) {
            float left = 0.0f;
            float diag = 0.0f;              // prev[0] == 0 always
            #pragma unroll
            for (int kk = 0; kk < LL; kk++) {
                float aa = As[jj * LL + kk];
                float cc = Cs[jj * LL + kk];
                float up = prev[kk + 1];
                float dd = fmaf(aa, diag, aa);        // a*(diag+1), off-chain
                left = fmaf(cc, fmaxf(left, up), dd); // 8-cyc chain
                prev[kk + 1] = left;                  // safe: up consumed
                diag = up;                            // rotation: next diag
                if ((jj + 1 == len) && (kk + 1 == len)) final_v = left;
            }
        }

        g_calcs[b] = -logf(final_v / (float)len);
        __threadfence();
        int ticket = atomicAdd(&g_count, 1);
        if (ticket == BB - 1) {
            // deterministic ordered reduction by the last-arriving block
            volatile float* gc = g_calcs;
            float s = 0.0f;
            #pragma unroll
            for (int i = 0; i < BB; i++) s += gc[i];
            out[0] = s / (float)BB;
            g_count = 0;   // re-arm for next graph replay
        }
    }
}

extern "C" void kernel_launch(void* const* d_in, const int* in_sizes, int n_in,
                              void* d_out, int out_size) {
    const float* tp = (const float*)d_in[0];   // topic_prob [B, L, V] f32
    const int*   hl = (const int*)d_in[1];     // hard_label [B, L] i32
    float* out = (float*)d_out;
    calcs_fused<<<BB, LL * LL>>>(tp, hl, out);
}